// round 11
// baseline (speedup 1.0000x reference)
#include <cuda_runtime.h>
#include <cuda_bf16.h>
#include <math.h>

#define NN 100000
#define EE 1600000

#define SCAN_BS 512
#define SCAN_NB ((NN + SCAN_BS - 1) / SCAN_BS)   // 196

// ---------------- scratch (device globals; no allocation allowed) ----------------
__device__ float  g_deg[NN];
__device__ float  g_dinv[NN];
__device__ int    g_cnt[NN];
__device__ int    g_ptr[NN];
__device__ int    g_cur[NN];
__device__ int    g_bsum[SCAN_NB];
__device__ int    g_boff[SCAN_NB];
__device__ int2   g_edge[EE];       // CSR slot: {src, float_bits(norm)}
__device__ float4 g_h4[NN * 16];    // GEMM output (messages)
__device__ float4 g_gc4[NN * 16];   // aggregated + activated output
__device__ float  g_z[NN * 64];     // update gate Z
__device__ float  g_hr[NN * 64];    // H * R

// ---------------- fast activations (2-ulp class, saturation-safe) ----------------
__device__ __forceinline__ float f_sig(float x) {
    return __fdividef(1.0f, 1.0f + __expf(-x));
}
__device__ __forceinline__ float f_tanh(float x) {
    return 1.0f - __fdividef(2.0f, __expf(2.0f * x) + 1.0f);
}

// ---------------- tf32 helpers ----------------
__device__ __forceinline__ void tf32split(float x, unsigned& hi, unsigned& lo) {
    asm("cvt.rna.tf32.f32 %0, %1;" : "=r"(hi) : "f"(x));
    float r = x - __uint_as_float(hi);
    asm("cvt.rna.tf32.f32 %0, %1;" : "=r"(lo) : "f"(r));
}
__device__ __forceinline__ unsigned tf32rnd(float x) {
    unsigned h; asm("cvt.rna.tf32.f32 %0, %1;" : "=r"(h) : "f"(x)); return h;
}
__device__ __forceinline__ void mma_tf32(float* c, const unsigned* a, const unsigned* b) {
    asm volatile(
        "mma.sync.aligned.m16n8k8.row.col.f32.tf32.tf32.f32 "
        "{%0,%1,%2,%3}, {%4,%5,%6,%7}, {%8,%9}, {%0,%1,%2,%3};"
        : "+f"(c[0]), "+f"(c[1]), "+f"(c[2]), "+f"(c[3])
        : "r"(a[0]), "r"(a[1]), "r"(a[2]), "r"(a[3]), "r"(b[0]), "r"(b[1]));
}

// ---------------- prep ----------------
__global__ void k_init() {
    int i = blockIdx.x * blockDim.x + threadIdx.x;
    if (i < NN) { g_deg[i] = 1.0f; g_cnt[i] = 0; }
}

__global__ void k_count(const int* __restrict__ ei, const float* __restrict__ w) {
    int p = blockIdx.x * blockDim.x + threadIdx.x;
    if (p < EE / 2) {
        int2   c2 = __ldg((const int2*)(ei + EE) + p);
        float2 w2 = __ldg((const float2*)w + p);
        atomicAdd(&g_deg[c2.x], w2.x);
        atomicAdd(&g_cnt[c2.x], 1);
        atomicAdd(&g_deg[c2.y], w2.y);
        atomicAdd(&g_cnt[c2.y], 1);
    }
}

__global__ __launch_bounds__(SCAN_BS) void k_scan1() {
    __shared__ int sh[SCAN_BS];
    int t = threadIdx.x;
    int i = blockIdx.x * SCAN_BS + t;
    if (i < NN) {
        float d = g_deg[i];
        g_dinv[i] = (d > 0.0f) ? rsqrtf(d) : 0.0f;
    }
    int v = (i < NN) ? g_cnt[i] : 0;
    sh[t] = v;
    __syncthreads();
#pragma unroll
    for (int off = 1; off < SCAN_BS; off <<= 1) {
        int x = (t >= off) ? sh[t - off] : 0;
        __syncthreads();
        sh[t] += x;
        __syncthreads();
    }
    if (i < NN) g_ptr[i] = sh[t] - v;
    if (t == SCAN_BS - 1) g_bsum[blockIdx.x] = sh[t];
}

__global__ __launch_bounds__(256) void k_scan2() {
    __shared__ int sh[256];
    int t = threadIdx.x;
    int v = (t < SCAN_NB) ? g_bsum[t] : 0;
    sh[t] = v;
    __syncthreads();
#pragma unroll
    for (int off = 1; off < 256; off <<= 1) {
        int x = (t >= off) ? sh[t - off] : 0;
        __syncthreads();
        sh[t] += x;
        __syncthreads();
    }
    if (t < SCAN_NB) g_boff[t] = sh[t] - v;
}

__global__ __launch_bounds__(SCAN_BS) void k_scan3() {
    int i = blockIdx.x * SCAN_BS + threadIdx.x;
    if (i < NN) {
        int p = g_ptr[i] + g_boff[blockIdx.x];
        g_ptr[i] = p;
        g_cur[i] = p;
    }
}

__global__ void k_scatter(const int* __restrict__ ei, const float* __restrict__ w) {
    int p = blockIdx.x * blockDim.x + threadIdx.x;
    if (p < EE / 2) {
        int2   r2 = __ldg((const int2*)ei + p);
        int2   c2 = __ldg((const int2*)(ei + EE) + p);
        float2 w2 = __ldg((const float2*)w + p);
        float n0 = g_dinv[r2.x] * w2.x * g_dinv[c2.x];
        float n1 = g_dinv[r2.y] * w2.y * g_dinv[c2.y];
        int s0 = atomicAdd(&g_cur[c2.x], 1);
        int s1 = atomicAdd(&g_cur[c2.y], 1);
        g_edge[s0] = make_int2(r2.x, __float_as_int(n0));
        g_edge[s1] = make_int2(r2.y, __float_as_int(n1));
    }
}

// ---------------- dense GEMM (scalar, reverted from f32x2) ----------------
__device__ __forceinline__ void gemm64_body(const float* __restrict__ x,
                                            const float* __restrict__ W) {
    int c   = threadIdx.x & 63;
    int sub = threadIdx.x >> 6;
    float w[64];
#pragma unroll
    for (int k = 0; k < 64; k++) w[k] = __ldg(&W[k * 64 + c]);

    float* __restrict__ hout = (float*)g_h4;
    const int groups = NN / 4;
    for (int g = blockIdx.x; g < groups; g += gridDim.x) {
        int r = g * 4 + sub;
        const float4* xr = (const float4*)(x + (size_t)r * 64);
        float acc = 0.0f;
#pragma unroll
        for (int k4 = 0; k4 < 16; k4++) {
            float4 v = __ldg(xr + k4);
            acc = fmaf(v.x, w[4 * k4 + 0], acc);
            acc = fmaf(v.y, w[4 * k4 + 1], acc);
            acc = fmaf(v.z, w[4 * k4 + 2], acc);
            acc = fmaf(v.w, w[4 * k4 + 3], acc);
        }
        hout[(size_t)r * 64 + c] = acc;
    }
}

__global__ __launch_bounds__(256) void k_gemm_x(const float* __restrict__ x,
                                                const float* __restrict__ W) {
    gemm64_body(x, W);
}

__global__ __launch_bounds__(256) void k_gemm_gc(const float* __restrict__ W) {
    gemm64_body((const float*)g_gc4, W);
}

// ---------------- fused aggregation (R9, L2-BW bound) ----------------
__global__ __launch_bounds__(256) void k_gather(const float* __restrict__ b, int relu) {
    int t = blockIdx.x * blockDim.x + threadIdx.x;
    int node = t >> 4;
    if (node >= NN) return;
    int l16 = t & 15;

    float s = g_dinv[node];
    s = s * s;
    float4 acc = g_h4[(size_t)node * 16 + l16];
    acc.x *= s; acc.y *= s; acc.z *= s; acc.w *= s;

    int j   = g_ptr[node];
    int end = g_cur[node];

    for (; j + 3 < end; j += 4) {
        int2 e0 = __ldg(&g_edge[j]);
        int2 e1 = __ldg(&g_edge[j + 1]);
        int2 e2 = __ldg(&g_edge[j + 2]);
        int2 e3 = __ldg(&g_edge[j + 3]);
        float4 v0 = __ldg(&g_h4[(size_t)e0.x * 16 + l16]);
        float4 v1 = __ldg(&g_h4[(size_t)e1.x * 16 + l16]);
        float4 v2 = __ldg(&g_h4[(size_t)e2.x * 16 + l16]);
        float4 v3 = __ldg(&g_h4[(size_t)e3.x * 16 + l16]);
        float n0 = __int_as_float(e0.y), n1 = __int_as_float(e1.y);
        float n2 = __int_as_float(e2.y), n3 = __int_as_float(e3.y);
        acc.x = fmaf(n0, v0.x, acc.x); acc.y = fmaf(n0, v0.y, acc.y);
        acc.z = fmaf(n0, v0.z, acc.z); acc.w = fmaf(n0, v0.w, acc.w);
        acc.x = fmaf(n1, v1.x, acc.x); acc.y = fmaf(n1, v1.y, acc.y);
        acc.z = fmaf(n1, v1.z, acc.z); acc.w = fmaf(n1, v1.w, acc.w);
        acc.x = fmaf(n2, v2.x, acc.x); acc.y = fmaf(n2, v2.y, acc.y);
        acc.z = fmaf(n2, v2.z, acc.z); acc.w = fmaf(n2, v2.w, acc.w);
        acc.x = fmaf(n3, v3.x, acc.x); acc.y = fmaf(n3, v3.y, acc.y);
        acc.z = fmaf(n3, v3.z, acc.z); acc.w = fmaf(n3, v3.w, acc.w);
    }
    for (; j < end; j++) {
        int2 e0 = __ldg(&g_edge[j]);
        float4 v0 = __ldg(&g_h4[(size_t)e0.x * 16 + l16]);
        float n0 = __int_as_float(e0.y);
        acc.x = fmaf(n0, v0.x, acc.x); acc.y = fmaf(n0, v0.y, acc.y);
        acc.z = fmaf(n0, v0.z, acc.z); acc.w = fmaf(n0, v0.w, acc.w);
    }

    float4 bb = __ldg(((const float4*)b) + l16);
    acc.x += bb.x; acc.y += bb.y; acc.z += bb.z; acc.w += bb.w;
    if (relu) {
        acc.x = fmaxf(acc.x, 0.0f); acc.y = fmaxf(acc.y, 0.0f);
        acc.z = fmaxf(acc.z, 0.0f); acc.w = fmaxf(acc.w, 0.0f);
    } else {
        acc.x = f_sig(acc.x); acc.y = f_sig(acc.y);
        acc.z = f_sig(acc.z); acc.w = f_sig(acc.w);
    }
    g_gc4[(size_t)node * 16 + l16] = acc;
}

// ================= GRU gates via tensor cores (3xTF32 mma.sync) =================
// K1 (k_zr): ZR[N,128] = [GC|H] @ [Wz|Wr]; Z=sig -> g_z, HR = H*sig(R) -> g_hr
// K2 (k_ht): Ht[N,64] = [GC|HR] @ Wh; out = Z*H + (1-Z)*tanh(Ht+bh)
// Block: 256 threads = 8 warps; warp (mhalf = w>>2) x (nq = w&3).
// Tile: 128 rows per iteration; W hi/lo staged once per block (persistent grid).

#define NT1 782                   // ceil(NN/128)
#define WSTRIDE1 132              // 128x128 W, padded row stride (banks: 132%32=4)
#define ASTRIDE  132
#define WSTRIDE2 68               // 128x64 Wh padded

__global__ void k_zr(const float* __restrict__ Hm,
                     const float* __restrict__ Wz, const float* __restrict__ bz,
                     const float* __restrict__ Wr, const float* __restrict__ br) {
    extern __shared__ float sm[];
    float* s_whi = sm;                         // [128*132]
    float* s_wlo = sm + 128 * WSTRIDE1;        // [128*132]
    float* s_a   = sm + 2 * 128 * WSTRIDE1;    // [128*132] fp32

    int tid = threadIdx.x;
    int w   = tid >> 5;
    int lane = tid & 31;
    int grp = lane >> 2, qid = lane & 3;
    int mhalf = w >> 2, nq = w & 3;
    const float* gc = (const float*)g_gc4;

    // Stage W = [Wz | Wr] hi/lo (once per block)
    for (int idx = tid; idx < 128 * 128; idx += 256) {
        int k = idx >> 7, n = idx & 127;
        float f = (n < 64) ? __ldg(&Wz[k * 64 + n]) : __ldg(&Wr[k * 64 + n - 64]);
        unsigned hi, lo; tf32split(f, hi, lo);
        s_whi[k * WSTRIDE1 + n] = __uint_as_float(hi);
        s_wlo[k * WSTRIDE1 + n] = __uint_as_float(lo);
    }

    for (int tile = blockIdx.x; tile < NT1; tile += gridDim.x) {
        int base = tile * 128;
        __syncthreads();
        // Stage A = [GC | H] fp32
        for (int idx = tid; idx < 128 * 128; idx += 256) {
            int row = idx >> 7, col = idx & 127;
            int node = base + row;
            float v = 0.0f;
            if (node < NN)
                v = (col < 64) ? __ldg(&gc[(size_t)node * 64 + col])
                               : __ldg(&Hm[(size_t)node * 64 + col - 64]);
            s_a[row * ASTRIDE + col] = v;
        }
        __syncthreads();

        float acc[4][4][4];
#pragma unroll
        for (int mt = 0; mt < 4; mt++)
#pragma unroll
            for (int nt = 0; nt < 4; nt++)
#pragma unroll
                for (int i = 0; i < 4; i++) acc[mt][nt][i] = 0.0f;

#pragma unroll
        for (int kt = 0; kt < 16; kt++) {
            unsigned ahi[4][4], alo[4][4];
            int kc = kt * 8 + qid;
#pragma unroll
            for (int mt = 0; mt < 4; mt++) {
                int r0 = mhalf * 64 + mt * 16 + grp;
                tf32split(s_a[r0 * ASTRIDE + kc],           ahi[mt][0], alo[mt][0]);
                tf32split(s_a[(r0 + 8) * ASTRIDE + kc],     ahi[mt][1], alo[mt][1]);
                tf32split(s_a[r0 * ASTRIDE + kc + 4],       ahi[mt][2], alo[mt][2]);
                tf32split(s_a[(r0 + 8) * ASTRIDE + kc + 4], ahi[mt][3], alo[mt][3]);
            }
#pragma unroll
            for (int nt = 0; nt < 4; nt++) {
                int nc = nq * 32 + nt * 8 + grp;
                int kr = kt * 8 + qid;
                unsigned bhi[2] = { __float_as_uint(s_whi[kr * WSTRIDE1 + nc]),
                                    __float_as_uint(s_whi[(kr + 4) * WSTRIDE1 + nc]) };
                unsigned blo[2] = { __float_as_uint(s_wlo[kr * WSTRIDE1 + nc]),
                                    __float_as_uint(s_wlo[(kr + 4) * WSTRIDE1 + nc]) };
#pragma unroll
                for (int mt = 0; mt < 4; mt++) {
                    mma_tf32(acc[mt][nt], alo[mt], bhi);
                    mma_tf32(acc[mt][nt], ahi[mt], blo);
                    mma_tf32(acc[mt][nt], ahi[mt], bhi);
                }
            }
        }

        // Epilogue: Z / HR
#pragma unroll
        for (int mt = 0; mt < 4; mt++) {
            int r0 = base + mhalf * 64 + mt * 16 + grp;
            int r1 = r0 + 8;
#pragma unroll
            for (int nt = 0; nt < 4; nt++) {
                int col = nq * 32 + nt * 8 + 2 * qid;
                if (col < 64) {
                    float2 bb = __ldg((const float2*)(bz + col));
                    if (r0 < NN) {
                        float2 z = make_float2(f_sig(acc[mt][nt][0] + bb.x),
                                               f_sig(acc[mt][nt][1] + bb.y));
                        *(float2*)(g_z + (size_t)r0 * 64 + col) = z;
                    }
                    if (r1 < NN) {
                        float2 z = make_float2(f_sig(acc[mt][nt][2] + bb.x),
                                               f_sig(acc[mt][nt][3] + bb.y));
                        *(float2*)(g_z + (size_t)r1 * 64 + col) = z;
                    }
                } else {
                    int cr = col - 64;
                    float2 bb = __ldg((const float2*)(br + cr));
                    if (r0 < NN) {
                        float2 h = __ldg((const float2*)(Hm + (size_t)r0 * 64 + cr));
                        float2 o = make_float2(h.x * f_sig(acc[mt][nt][0] + bb.x),
                                               h.y * f_sig(acc[mt][nt][1] + bb.y));
                        *(float2*)(g_hr + (size_t)r0 * 64 + cr) = o;
                    }
                    if (r1 < NN) {
                        float2 h = __ldg((const float2*)(Hm + (size_t)r1 * 64 + cr));
                        float2 o = make_float2(h.x * f_sig(acc[mt][nt][2] + bb.x),
                                               h.y * f_sig(acc[mt][nt][3] + bb.y));
                        *(float2*)(g_hr + (size_t)r1 * 64 + cr) = o;
                    }
                }
            }
        }
    }
}

__global__ void k_ht(const float* __restrict__ Hm,
                     const float* __restrict__ Wh, const float* __restrict__ bh,
                     float* __restrict__ out) {
    extern __shared__ float sm[];
    float* s_whi = sm;                         // [128*68]
    float* s_wlo = sm + 128 * WSTRIDE2;
    float* s_a   = sm + 2 * 128 * WSTRIDE2;    // [128*132] fp32

    int tid = threadIdx.x;
    int w   = tid >> 5;
    int lane = tid & 31;
    int grp = lane >> 2, qid = lane & 3;
    int mhalf = w >> 2, nq = w & 3;
    const float* gc = (const float*)g_gc4;

    for (int idx = tid; idx < 128 * 64; idx += 256) {
        int k = idx >> 6, n = idx & 63;
        unsigned hi, lo; tf32split(__ldg(&Wh[k * 64 + n]), hi, lo);
        s_whi[k * WSTRIDE2 + n] = __uint_as_float(hi);
        s_wlo[k * WSTRIDE2 + n] = __uint_as_float(lo);
    }

    for (int tile = blockIdx.x; tile < NT1; tile += gridDim.x) {
        int base = tile * 128;
        __syncthreads();
        for (int idx = tid; idx < 128 * 128; idx += 256) {
            int row = idx >> 7, col = idx & 127;
            int node = base + row;
            float v = 0.0f;
            if (node < NN)
                v = (col < 64) ? __ldg(&gc[(size_t)node * 64 + col])
                               : __ldg(&g_hr[(size_t)node * 64 + col - 64]);
            s_a[row * ASTRIDE + col] = v;
        }
        __syncthreads();

        float acc[4][2][4];
#pragma unroll
        for (int mt = 0; mt < 4; mt++)
#pragma unroll
            for (int nt = 0; nt < 2; nt++)
#pragma unroll
                for (int i = 0; i < 4; i++) acc[mt][nt][i] = 0.0f;

#pragma unroll
        for (int kt = 0; kt < 16; kt++) {
            unsigned ahi[4][4], alo[4][4];
            int kc = kt * 8 + qid;
#pragma unroll
            for (int mt = 0; mt < 4; mt++) {
                int r0 = mhalf * 64 + mt * 16 + grp;
                tf32split(s_a[r0 * ASTRIDE + kc],           ahi[mt][0], alo[mt][0]);
                tf32split(s_a[(r0 + 8) * ASTRIDE + kc],     ahi[mt][1], alo[mt][1]);
                tf32split(s_a[r0 * ASTRIDE + kc + 4],       ahi[mt][2], alo[mt][2]);
                tf32split(s_a[(r0 + 8) * ASTRIDE + kc + 4], ahi[mt][3], alo[mt][3]);
            }
#pragma unroll
            for (int nt = 0; nt < 2; nt++) {
                int nc = nq * 16 + nt * 8 + grp;
                int kr = kt * 8 + qid;
                unsigned bhi[2] = { __float_as_uint(s_whi[kr * WSTRIDE2 + nc]),
                                    __float_as_uint(s_whi[(kr + 4) * WSTRIDE2 + nc]) };
                unsigned blo[2] = { __float_as_uint(s_wlo[kr * WSTRIDE2 + nc]),
                                    __float_as_uint(s_wlo[(kr + 4) * WSTRIDE2 + nc]) };
#pragma unroll
                for (int mt = 0; mt < 4; mt++) {
                    mma_tf32(acc[mt][nt], alo[mt], bhi);
                    mma_tf32(acc[mt][nt], ahi[mt], blo);
                    mma_tf32(acc[mt][nt], ahi[mt], bhi);
                }
            }
        }

        // Epilogue: out = Z*H + (1-Z)*tanh(Ht + bh)
#pragma unroll
        for (int mt = 0; mt < 4; mt++) {
            int r0 = base + mhalf * 64 + mt * 16 + grp;
            int r1 = r0 + 8;
#pragma unroll
            for (int nt = 0; nt < 2; nt++) {
                int col = nq * 16 + nt * 8 + 2 * qid;
                float2 bb = __ldg((const float2*)(bh + col));
                if (r0 < NN) {
                    float2 z = __ldg((const float2*)(g_z + (size_t)r0 * 64 + col));
                    float2 h = __ldg((const float2*)(Hm  + (size_t)r0 * 64 + col));
                    float t0 = f_tanh(acc[mt][nt][0] + bb.x);
                    float t1 = f_tanh(acc[mt][nt][1] + bb.y);
                    float2 o = make_float2(z.x * h.x + (1.0f - z.x) * t0,
                                           z.y * h.y + (1.0f - z.y) * t1);
                    *(float2*)(out + (size_t)r0 * 64 + col) = o;
                }
                if (r1 < NN) {
                    float2 z = __ldg((const float2*)(g_z + (size_t)r1 * 64 + col));
                    float2 h = __ldg((const float2*)(Hm  + (size_t)r1 * 64 + col));
                    float t0 = f_tanh(acc[mt][nt][2] + bb.x);
                    float t1 = f_tanh(acc[mt][nt][3] + bb.y);
                    float2 o = make_float2(z.x * h.x + (1.0f - z.x) * t0,
                                           z.y * h.y + (1.0f - z.y) * t1);
                    *(float2*)(out + (size_t)r1 * 64 + col) = o;
                }
            }
        }
    }
}

// ---------------- launch ----------------
extern "C" void kernel_launch(void* const* d_in, const int* in_sizes, int n_in,
                              void* d_out, int out_size) {
    const float* X  = (const float*)d_in[0];
    const int*   EI = (const int*)d_in[1];     // int32 (JAX default x64 disabled)
    const float* EW = (const float*)d_in[2];
    const float* H  = (const float*)d_in[3];
    const float* W1 = (const float*)d_in[4];
    const float* b1 = (const float*)d_in[5];
    const float* W2 = (const float*)d_in[6];
    const float* b2 = (const float*)d_in[7];
    const float* Wz = (const float*)d_in[8];
    const float* bz = (const float*)d_in[9];
    const float* Wr = (const float*)d_in[10];
    const float* br = (const float*)d_in[11];
    const float* Wh = (const float*)d_in[12];
    const float* bh = (const float*)d_in[13];
    float* out = (float*)d_out;

    const int TB = 256;
    const int nBlkN   = (NN + TB - 1) / TB;
    const int nBlkE2  = (EE / 2 + TB - 1) / TB;
    const int nBlkGat = (NN * 16 + TB - 1) / TB;

    const int SM1 = (3 * 128 * WSTRIDE1) * 4;                      // 202,752 B
    const int SM2 = (2 * 128 * WSTRIDE2 + 128 * ASTRIDE) * 4;      // 137,216 B
    cudaFuncSetAttribute(k_zr, cudaFuncAttributeMaxDynamicSharedMemorySize, SM1);
    cudaFuncSetAttribute(k_ht, cudaFuncAttributeMaxDynamicSharedMemorySize, SM2);

    // prep + layer pipeline (k_gemm_x at launch #4 for ncu calibration)
    k_init<<<nBlkN, TB>>>();
    k_count<<<nBlkE2, TB>>>(EI, EW);
    k_scan1<<<SCAN_NB, SCAN_BS>>>();
    k_gemm_x<<<1024, TB>>>(X, W1);
    k_scan2<<<1, 256>>>();
    k_scan3<<<SCAN_NB, SCAN_BS>>>();
    k_scatter<<<nBlkE2, TB>>>(EI, EW);

    k_gather<<<nBlkGat, TB>>>(b1, 1);   // relu -> g_gc4

    k_gemm_gc<<<1024, TB>>>(W2);
    k_gather<<<nBlkGat, TB>>>(b2, 0);   // sigmoid -> g_gc4

    // GRU gates on tensor cores
    k_zr<<<148, 256, SM1>>>(H, Wz, bz, Wr, br);
    k_ht<<<148, 256, SM2>>>(H, Wh, bh, out);
}

// round 13
// speedup vs baseline: 1.8230x; 1.8230x over previous
#include <cuda_runtime.h>
#include <cuda_bf16.h>
#include <math.h>

#define NN 100000
#define EE 1600000

#define SCAN_BS 512
#define SCAN_NB ((NN + SCAN_BS - 1) / SCAN_BS)   // 196

// ---------------- scratch (device globals; no allocation allowed) ----------------
__device__ float  g_deg[NN];
__device__ float  g_dinv[NN];
__device__ int    g_cnt[NN];
__device__ int    g_ptr[NN];
__device__ int    g_cur[NN];
__device__ int    g_bsum[SCAN_NB];
__device__ int    g_boff[SCAN_NB];
__device__ int2   g_edge[EE];       // CSR slot: {src, float_bits(norm)}
__device__ float4 g_h4[NN * 16];    // GEMM output (messages)
__device__ float4 g_gc4[NN * 16];   // aggregated + activated output

// ---------------- fast activations (2-ulp class, saturation-safe) ----------------
__device__ __forceinline__ float f_sig(float x) {
    return __fdividef(1.0f, 1.0f + __expf(-x));
}
__device__ __forceinline__ float f_tanh(float x) {
    return 1.0f - __fdividef(2.0f, __expf(2.0f * x) + 1.0f);
}

// ---------------- prep ----------------
__global__ void k_init() {
    int i = blockIdx.x * blockDim.x + threadIdx.x;
    if (i < NN) { g_deg[i] = 1.0f; g_cnt[i] = 0; }
}

__global__ void k_count(const int* __restrict__ ei, const float* __restrict__ w) {
    int p = blockIdx.x * blockDim.x + threadIdx.x;
    if (p < EE / 2) {
        int2   c2 = __ldg((const int2*)(ei + EE) + p);
        float2 w2 = __ldg((const float2*)w + p);
        atomicAdd(&g_deg[c2.x], w2.x);
        atomicAdd(&g_cnt[c2.x], 1);
        atomicAdd(&g_deg[c2.y], w2.y);
        atomicAdd(&g_cnt[c2.y], 1);
    }
}

__global__ __launch_bounds__(SCAN_BS) void k_scan1() {
    __shared__ int sh[SCAN_BS];
    int t = threadIdx.x;
    int i = blockIdx.x * SCAN_BS + t;
    if (i < NN) {
        float d = g_deg[i];
        g_dinv[i] = (d > 0.0f) ? rsqrtf(d) : 0.0f;
    }
    int v = (i < NN) ? g_cnt[i] : 0;
    sh[t] = v;
    __syncthreads();
#pragma unroll
    for (int off = 1; off < SCAN_BS; off <<= 1) {
        int x = (t >= off) ? sh[t - off] : 0;
        __syncthreads();
        sh[t] += x;
        __syncthreads();
    }
    if (i < NN) g_ptr[i] = sh[t] - v;
    if (t == SCAN_BS - 1) g_bsum[blockIdx.x] = sh[t];
}

__global__ __launch_bounds__(256) void k_scan2() {
    __shared__ int sh[256];
    int t = threadIdx.x;
    int v = (t < SCAN_NB) ? g_bsum[t] : 0;
    sh[t] = v;
    __syncthreads();
#pragma unroll
    for (int off = 1; off < 256; off <<= 1) {
        int x = (t >= off) ? sh[t - off] : 0;
        __syncthreads();
        sh[t] += x;
        __syncthreads();
    }
    if (t < SCAN_NB) g_boff[t] = sh[t] - v;
}

__global__ __launch_bounds__(SCAN_BS) void k_scan3() {
    int i = blockIdx.x * SCAN_BS + threadIdx.x;
    if (i < NN) {
        int p = g_ptr[i] + g_boff[blockIdx.x];
        g_ptr[i] = p;
        g_cur[i] = p;
    }
}

__global__ void k_scatter(const int* __restrict__ ei, const float* __restrict__ w) {
    int p = blockIdx.x * blockDim.x + threadIdx.x;
    if (p < EE / 2) {
        int2   r2 = __ldg((const int2*)ei + p);
        int2   c2 = __ldg((const int2*)(ei + EE) + p);
        float2 w2 = __ldg((const float2*)w + p);
        float n0 = g_dinv[r2.x] * w2.x * g_dinv[c2.x];
        float n1 = g_dinv[r2.y] * w2.y * g_dinv[c2.y];
        int s0 = atomicAdd(&g_cur[c2.x], 1);
        int s1 = atomicAdd(&g_cur[c2.y], 1);
        g_edge[s0] = make_int2(r2.x, __float_as_int(n0));
        g_edge[s1] = make_int2(r2.y, __float_as_int(n1));
    }
}

// ---------------- dense GEMM, smem-staged x tiles ----------------
// R11 profile: warp-uniform LDG.128 cost ~4 L1 wavefronts each (L1=54.5%, 88us).
// Fix: coalesced global->smem stage (1 float4/thread), compute from smem
// broadcast LDS. 16 rows/tile, 4 rows/thread (ILP=4).
__device__ __forceinline__ void gemm64_body(const float* __restrict__ x,
                                            const float* __restrict__ W) {
    int t   = threadIdx.x;
    int c   = t & 63;
    int sub = t >> 6;                 // 0..3
    float w[64];
#pragma unroll
    for (int k = 0; k < 64; k++) w[k] = __ldg(&W[k * 64 + c]);

    __shared__ float4 s_x[16][16];    // 16 rows x 64 floats

    float* __restrict__ hout = (float*)g_h4;
    const int tiles = NN / 16;        // 6250
    for (int tile = blockIdx.x; tile < tiles; tile += gridDim.x) {
        int base = tile * 16;
        __syncthreads();
        // coalesced stage: thread t loads float4 #t of the 4KB tile
        s_x[t >> 4][t & 15] = __ldg((const float4*)(x + (size_t)(base + (t >> 4)) * 64) + (t & 15));
        __syncthreads();

        float acc[4] = {0.0f, 0.0f, 0.0f, 0.0f};
#pragma unroll
        for (int k4 = 0; k4 < 16; k4++) {
#pragma unroll
            for (int rr = 0; rr < 4; rr++) {
                float4 v = s_x[sub + rr * 4][k4];   // warp-uniform -> LDS broadcast
                acc[rr] = fmaf(v.x, w[4 * k4 + 0], acc[rr]);
                acc[rr] = fmaf(v.y, w[4 * k4 + 1], acc[rr]);
                acc[rr] = fmaf(v.z, w[4 * k4 + 2], acc[rr]);
                acc[rr] = fmaf(v.w, w[4 * k4 + 3], acc[rr]);
            }
        }
#pragma unroll
        for (int rr = 0; rr < 4; rr++)
            hout[(size_t)(base + sub + rr * 4) * 64 + c] = acc[rr];
    }
}

__global__ __launch_bounds__(256) void k_gemm_x(const float* __restrict__ x,
                                                const float* __restrict__ W) {
    gemm64_body(x, W);
}

__global__ __launch_bounds__(256) void k_gemm_gc(const float* __restrict__ W) {
    gemm64_body((const float*)g_gc4, W);
}

// ---------------- fused aggregation (R9, L2-BW bound) ----------------
__global__ __launch_bounds__(256) void k_gather(const float* __restrict__ b, int relu) {
    int t = blockIdx.x * blockDim.x + threadIdx.x;
    int node = t >> 4;
    if (node >= NN) return;
    int l16 = t & 15;

    float s = g_dinv[node];
    s = s * s;
    float4 acc = g_h4[(size_t)node * 16 + l16];
    acc.x *= s; acc.y *= s; acc.z *= s; acc.w *= s;

    int j   = g_ptr[node];
    int end = g_cur[node];

    for (; j + 3 < end; j += 4) {
        int2 e0 = __ldg(&g_edge[j]);
        int2 e1 = __ldg(&g_edge[j + 1]);
        int2 e2 = __ldg(&g_edge[j + 2]);
        int2 e3 = __ldg(&g_edge[j + 3]);
        float4 v0 = __ldg(&g_h4[(size_t)e0.x * 16 + l16]);
        float4 v1 = __ldg(&g_h4[(size_t)e1.x * 16 + l16]);
        float4 v2 = __ldg(&g_h4[(size_t)e2.x * 16 + l16]);
        float4 v3 = __ldg(&g_h4[(size_t)e3.x * 16 + l16]);
        float n0 = __int_as_float(e0.y), n1 = __int_as_float(e1.y);
        float n2 = __int_as_float(e2.y), n3 = __int_as_float(e3.y);
        acc.x = fmaf(n0, v0.x, acc.x); acc.y = fmaf(n0, v0.y, acc.y);
        acc.z = fmaf(n0, v0.z, acc.z); acc.w = fmaf(n0, v0.w, acc.w);
        acc.x = fmaf(n1, v1.x, acc.x); acc.y = fmaf(n1, v1.y, acc.y);
        acc.z = fmaf(n1, v1.z, acc.z); acc.w = fmaf(n1, v1.w, acc.w);
        acc.x = fmaf(n2, v2.x, acc.x); acc.y = fmaf(n2, v2.y, acc.y);
        acc.z = fmaf(n2, v2.z, acc.z); acc.w = fmaf(n2, v2.w, acc.w);
        acc.x = fmaf(n3, v3.x, acc.x); acc.y = fmaf(n3, v3.y, acc.y);
        acc.z = fmaf(n3, v3.z, acc.z); acc.w = fmaf(n3, v3.w, acc.w);
    }
    for (; j < end; j++) {
        int2 e0 = __ldg(&g_edge[j]);
        float4 v0 = __ldg(&g_h4[(size_t)e0.x * 16 + l16]);
        float n0 = __int_as_float(e0.y);
        acc.x = fmaf(n0, v0.x, acc.x); acc.y = fmaf(n0, v0.y, acc.y);
        acc.z = fmaf(n0, v0.z, acc.z); acc.w = fmaf(n0, v0.w, acc.w);
    }

    float4 bb = __ldg(((const float4*)b) + l16);
    acc.x += bb.x; acc.y += bb.y; acc.z += bb.z; acc.w += bb.w;
    if (relu) {
        acc.x = fmaxf(acc.x, 0.0f); acc.y = fmaxf(acc.y, 0.0f);
        acc.z = fmaxf(acc.z, 0.0f); acc.w = fmaxf(acc.w, 0.0f);
    } else {
        acc.x = f_sig(acc.x); acc.y = f_sig(acc.y);
        acc.z = f_sig(acc.z); acc.w = f_sig(acc.w);
    }
    g_gc4[(size_t)node * 16 + l16] = acc;
}

// ---------------- fused GRU gates (R9 scalar, 8 rows/epoch) ----------------
#define GROWS 8
__global__ __launch_bounds__(192) void k_gates(const float* __restrict__ Hm,
                                               const float* __restrict__ Wz, const float* __restrict__ bz,
                                               const float* __restrict__ Wr, const float* __restrict__ br,
                                               const float* __restrict__ Wh, const float* __restrict__ bh,
                                               float* __restrict__ out) {
    int t = threadIdx.x;
    int gate = t >> 6;
    int c = t & 63;
    const float* W = (gate == 0) ? Wz : (gate == 1) ? Wr : Wh;
    float bias = ((gate == 0) ? bz : (gate == 1) ? br : bh)[c];
    float w[128];
#pragma unroll
    for (int k = 0; k < 128; k++) w[k] = __ldg(&W[k * 64 + c]);

    __shared__ float s_x[GROWS][128];    // [0:64) GC, [64:128) H
    __shared__ float s_zr[GROWS][128];   // [0:64) Z, [64:128) R
    __shared__ float s_ht[GROWS][64];

    const float* gc = (const float*)g_gc4;
    const int groups = NN / GROWS;       // 12500

    for (int g = blockIdx.x; g < groups; g += gridDim.x) {
        int r0 = g * GROWS;
        __syncthreads();
        if (t < 128) {
            const float* base = (t < 64) ? (gc + (size_t)r0 * 64 + t)
                                         : (Hm + (size_t)r0 * 64 + (t - 64));
#pragma unroll
            for (int rr = 0; rr < GROWS; rr++) s_x[rr][t] = __ldg(base + rr * 64);
        }
        __syncthreads();

        float acc[GROWS];
#pragma unroll
        for (int rr = 0; rr < GROWS; rr++) acc[rr] = bias;

        if (gate < 2) {
#pragma unroll
            for (int k4 = 0; k4 < 32; k4++) {
#pragma unroll
                for (int rr = 0; rr < GROWS; rr++) {
                    float4 v = ((const float4*)s_x[rr])[k4];
                    acc[rr] = fmaf(v.x, w[4 * k4 + 0], acc[rr]);
                    acc[rr] = fmaf(v.y, w[4 * k4 + 1], acc[rr]);
                    acc[rr] = fmaf(v.z, w[4 * k4 + 2], acc[rr]);
                    acc[rr] = fmaf(v.w, w[4 * k4 + 3], acc[rr]);
                }
            }
#pragma unroll
            for (int rr = 0; rr < GROWS; rr++)
                s_zr[rr][gate * 64 + c] = f_sig(acc[rr]);
        } else {
#pragma unroll
            for (int k4 = 0; k4 < 16; k4++) {      // GC half
#pragma unroll
                for (int rr = 0; rr < GROWS; rr++) {
                    float4 v = ((const float4*)s_x[rr])[k4];
                    acc[rr] = fmaf(v.x, w[4 * k4 + 0], acc[rr]);
                    acc[rr] = fmaf(v.y, w[4 * k4 + 1], acc[rr]);
                    acc[rr] = fmaf(v.z, w[4 * k4 + 2], acc[rr]);
                    acc[rr] = fmaf(v.w, w[4 * k4 + 3], acc[rr]);
                }
            }
        }
        __syncthreads();

        if (gate == 2) {
#pragma unroll
            for (int k4 = 0; k4 < 16; k4++) {      // (H*R) half
#pragma unroll
                for (int rr = 0; rr < GROWS; rr++) {
                    float4 hv = ((const float4*)s_x[rr])[16 + k4];
                    float4 rv = ((const float4*)s_zr[rr])[16 + k4];
                    acc[rr] = fmaf(hv.x * rv.x, w[64 + 4 * k4 + 0], acc[rr]);
                    acc[rr] = fmaf(hv.y * rv.y, w[64 + 4 * k4 + 1], acc[rr]);
                    acc[rr] = fmaf(hv.z * rv.z, w[64 + 4 * k4 + 2], acc[rr]);
                    acc[rr] = fmaf(hv.w * rv.w, w[64 + 4 * k4 + 3], acc[rr]);
                }
            }
#pragma unroll
            for (int rr = 0; rr < GROWS; rr++) s_ht[rr][c] = f_tanh(acc[rr]);
        }
        __syncthreads();

        if (gate == 0) {
#pragma unroll
            for (int rr = 0; rr < GROWS; rr++) {
                float z  = s_zr[rr][c];
                float hv = s_x[rr][64 + c];
                out[(size_t)(r0 + rr) * 64 + c] = z * hv + (1.0f - z) * s_ht[rr][c];
            }
        }
    }
}

// ---------------- launch ----------------
extern "C" void kernel_launch(void* const* d_in, const int* in_sizes, int n_in,
                              void* d_out, int out_size) {
    const float* X  = (const float*)d_in[0];
    const int*   EI = (const int*)d_in[1];     // int32 (JAX default x64 disabled)
    const float* EW = (const float*)d_in[2];
    const float* H  = (const float*)d_in[3];
    const float* W1 = (const float*)d_in[4];
    const float* b1 = (const float*)d_in[5];
    const float* W2 = (const float*)d_in[6];
    const float* b2 = (const float*)d_in[7];
    const float* Wz = (const float*)d_in[8];
    const float* bz = (const float*)d_in[9];
    const float* Wr = (const float*)d_in[10];
    const float* br = (const float*)d_in[11];
    const float* Wh = (const float*)d_in[12];
    const float* bh = (const float*)d_in[13];
    float* out = (float*)d_out;

    const int TB = 256;
    const int nBlkN   = (NN + TB - 1) / TB;
    const int nBlkE2  = (EE / 2 + TB - 1) / TB;
    const int nBlkGat = (NN * 16 + TB - 1) / TB;

    // prep + layer pipeline (new k_gemm_x at launch #4 for direct verification)
    k_init<<<nBlkN, TB>>>();
    k_count<<<nBlkE2, TB>>>(EI, EW);
    k_scan1<<<SCAN_NB, SCAN_BS>>>();
    k_gemm_x<<<1024, TB>>>(X, W1);
    k_scan2<<<1, 256>>>();
    k_scan3<<<SCAN_NB, SCAN_BS>>>();
    k_scatter<<<nBlkE2, TB>>>(EI, EW);

    k_gather<<<nBlkGat, TB>>>(b1, 1);   // relu -> g_gc4

    k_gemm_gc<<<1024, TB>>>(W2);
    k_gather<<<nBlkGat, TB>>>(b2, 0);   // sigmoid -> g_gc4

    k_gates<<<592, 192>>>(H, Wz, bz, Wr, br, Wh, bh, out);
}